// round 2
// baseline (speedup 1.0000x reference)
#include <cuda_runtime.h>

#define NOBJ   4096
#define DIM    1024
#define DIM2   2048
#define NREL   8
#define NPAIR  65536
#define NI_CHUNK 16
#define ICHUNK  64   // DIM / NI_CHUNK

// Scratch (device globals — no allocation allowed)
__device__ float g_Mpart[NI_CHUNK * NREL * DIM2];  // split-K partials, 1 MB
__device__ float g_M[NREL * DIM2];                 // fused weight M = W2 @ W1, 64 KB
__device__ float g_c[NREL];                        // fused bias c = W2@b1 + b2
__device__ float g_U[NOBJ * 16];                   // per-object projections, 256 KB

// ---------------------------------------------------------------------------
// Stage A: partial M[r][j] = sum_{i in chunk} W2[r][i] * W1[i][j]
// grid (8 j-chunks, 16 i-chunks) x 256 threads. W1 read exactly once (8 MB).
// ---------------------------------------------------------------------------
__global__ void m_partial_kernel(const float* __restrict__ W1,
                                 const float* __restrict__ W2) {
    __shared__ float sW2[NREL][ICHUNK];
    const int bx = blockIdx.x;     // j chunk: 256 consecutive j
    const int by = blockIdx.y;     // i chunk: 64 consecutive i
    const int tx = threadIdx.x;

    for (int t = tx; t < NREL * ICHUNK; t += 256) {
        int r = t / ICHUNK, ii = t % ICHUNK;
        sW2[r][ii] = W2[r * DIM + by * ICHUNK + ii];
    }
    __syncthreads();

    const int j = bx * 256 + tx;
    float acc[NREL];
#pragma unroll
    for (int r = 0; r < NREL; r++) acc[r] = 0.f;

    const int ibase = by * ICHUNK;
#pragma unroll 4
    for (int ii = 0; ii < ICHUNK; ii++) {
        float w1 = W1[(ibase + ii) * DIM2 + j];   // coalesced over tx
#pragma unroll
        for (int r = 0; r < NREL; r++) acc[r] += sW2[r][ii] * w1;
    }
#pragma unroll
    for (int r = 0; r < NREL; r++)
        g_Mpart[(by * NREL + r) * DIM2 + j] = acc[r];
}

// Stage B: deterministic fixed-order reduction over the 16 i-chunks.
__global__ void m_reduce_kernel() {
    const int g = blockIdx.x * 256 + threadIdx.x;  // 0..16383
    float s = 0.f;
#pragma unroll
    for (int by = 0; by < NI_CHUNK; by++)
        s += g_Mpart[by * (NREL * DIM2) + g];
    g_M[g] = s;
}

// c[r] = sum_i b1[i] * W2[r][i] + b2[r]. One warp per r.
__global__ void c_kernel(const float* __restrict__ W2,
                         const float* __restrict__ b1,
                         const float* __restrict__ b2) {
    const int w    = threadIdx.x >> 5;   // 0..7
    const int lane = threadIdx.x & 31;
    float s = 0.f;
    for (int i = lane; i < DIM; i += 32) s += b1[i] * W2[w * DIM + i];
#pragma unroll
    for (int off = 16; off; off >>= 1) s += __shfl_xor_sync(0xffffffffu, s, off);
    if (lane == 0) g_c[w] = s + b2[w];
}

// ---------------------------------------------------------------------------
// U[o][j] = sum_d feats[o][d] * Mrow_j[d]
//   j in [0,8):  Mrow_j = M[j][0:1024]      (subject projection)
//   j in [8,16): Mrow_j = M[j-8][1024:2048] (object projection)
// One warp per 4 objects; float4 loads; M (64 KB) stays hot in L1/L2.
// grid 128 x 256 threads -> 1024 warps x 4 objects = 4096.
// ---------------------------------------------------------------------------
__global__ void u_kernel(const float* __restrict__ feats) {
    const int wid  = (blockIdx.x * blockDim.x + threadIdx.x) >> 5;  // 0..1023
    const int lane = threadIdx.x & 31;
    const int obase = wid * 4;
    const float4* __restrict__ f4 = (const float4*)feats;

    float acc[4][16];
#pragma unroll
    for (int k = 0; k < 4; k++)
#pragma unroll
        for (int j = 0; j < 16; j++) acc[k][j] = 0.f;

#pragma unroll 1
    for (int t = 0; t < 8; t++) {          // 8 x 32 lanes x float4 = 1024 d
        const int idx = t * 32 + lane;
        float4 f[4];
#pragma unroll
        for (int k = 0; k < 4; k++) f[k] = f4[(obase + k) * 256 + idx];
#pragma unroll
        for (int j = 0; j < 16; j++) {
            const float4* __restrict__ m4 =
                (const float4*)(g_M + (j & 7) * DIM2 + (j >> 3) * DIM);
            float4 m = __ldg(&m4[idx]);
#pragma unroll
            for (int k = 0; k < 4; k++) {
                acc[k][j] += f[k].x * m.x;
                acc[k][j] += f[k].y * m.y;
                acc[k][j] += f[k].z * m.z;
                acc[k][j] += f[k].w * m.w;
            }
        }
    }

    // butterfly reduce each of the 64 partials; lane j stores column j
#pragma unroll
    for (int k = 0; k < 4; k++) {
#pragma unroll
        for (int j = 0; j < 16; j++) {
            float v = acc[k][j];
#pragma unroll
            for (int off = 16; off; off >>= 1)
                v += __shfl_xor_sync(0xffffffffu, v, off);
            if (lane == j) g_U[(obase + k) * 16 + j] = v;
        }
    }
}

// ---------------------------------------------------------------------------
// out[p][r] = U[s_p][r] + U[o_p][8+r] + c[r]
// pairs are int32 (JAX downcasts int64 without x64 mode): int2 per pair.
// ---------------------------------------------------------------------------
__global__ void gather_kernel(const int* __restrict__ pairs,
                              float* __restrict__ out) {
    const int p = blockIdx.x * 256 + threadIdx.x;  // 0..65535
    int2 pr = ((const int2*)pairs)[p];
    const int s = pr.x;
    const int o = pr.y;
    const float4* __restrict__ U4 = (const float4*)g_U;
    float4 a0 = U4[s * 4 + 0];
    float4 a1 = U4[s * 4 + 1];
    float4 b0 = U4[o * 4 + 2];
    float4 b1 = U4[o * 4 + 3];
    float4 c0 = ((const float4*)g_c)[0];
    float4 c1 = ((const float4*)g_c)[1];
    float4 o0, o1;
    o0.x = a0.x + b0.x + c0.x;  o0.y = a0.y + b0.y + c0.y;
    o0.z = a0.z + b0.z + c0.z;  o0.w = a0.w + b0.w + c0.w;
    o1.x = a1.x + b1.x + c1.x;  o1.y = a1.y + b1.y + c1.y;
    o1.z = a1.z + b1.z + c1.z;  o1.w = a1.w + b1.w + c1.w;
    ((float4*)out)[p * 2 + 0] = o0;
    ((float4*)out)[p * 2 + 1] = o1;
}

extern "C" void kernel_launch(void* const* d_in, const int* in_sizes, int n_in,
                              void* d_out, int out_size) {
    const float* feats = (const float*)d_in[0];   // (4096, 1024) f32
    const int*   pairs = (const int*)d_in[1];     // (65536, 2) i32
    const float* W1    = (const float*)d_in[2];   // (1024, 2048) f32
    const float* b1    = (const float*)d_in[3];   // (1024,) f32
    const float* W2    = (const float*)d_in[4];   // (8, 1024) f32
    const float* b2    = (const float*)d_in[5];   // (8,) f32
    float*       out   = (float*)d_out;           // (65536, 8) f32

    m_partial_kernel<<<dim3(8, 16), 256>>>(W1, W2);
    m_reduce_kernel<<<64, 256>>>();
    c_kernel<<<1, 256>>>(W2, b1, b2);
    u_kernel<<<128, 256>>>(feats);
    gather_kernel<<<256, 256>>>(pairs, out);
}

// round 3
// speedup vs baseline: 1.2685x; 1.2685x over previous
#include <cuda_runtime.h>

#define NOBJ   4096
#define DIM    1024
#define DIM2   2048
#define NREL   8
#define NPAIR  65536
#define NI_CHUNK 16
#define ICHUNK  64   // DIM / NI_CHUNK

// Scratch (device globals — no allocation allowed)
__device__ float g_Mpart[NI_CHUNK * NREL * DIM2];  // split-K partials, 1 MB
__device__ float g_M[NREL * DIM2];                 // fused weight M = W2 @ W1, 64 KB
__device__ float g_c[NREL];                        // fused bias c = W2@b1 + b2
__device__ float g_U[NOBJ * 16];                   // per-object projections, 256 KB

// Packed fp32x2 FMA: d = a*b + d elementwise on (lo,hi) pairs.
__device__ __forceinline__ void ffma2(unsigned long long& acc,
                                      unsigned long long a,
                                      unsigned long long b) {
    asm("fma.rn.f32x2 %0, %1, %2, %0;" : "+l"(acc) : "l"(a), "l"(b));
}

// ---------------------------------------------------------------------------
// Stage A: partial M[r][j] = sum_{i in chunk} W2[r][i] * W1[i][j]
// grid (8 j-chunks, 16 i-chunks) x 256 threads. W1 read exactly once (8 MB).
// ---------------------------------------------------------------------------
__global__ void m_partial_kernel(const float* __restrict__ W1,
                                 const float* __restrict__ W2) {
    __shared__ float sW2[NREL][ICHUNK];
    const int bx = blockIdx.x;     // j chunk: 256 consecutive j
    const int by = blockIdx.y;     // i chunk: 64 consecutive i
    const int tx = threadIdx.x;

    for (int t = tx; t < NREL * ICHUNK; t += 256) {
        int r = t / ICHUNK, ii = t % ICHUNK;
        sW2[r][ii] = W2[r * DIM + by * ICHUNK + ii];
    }
    __syncthreads();

    const int j = bx * 256 + tx;
    float acc[NREL];
#pragma unroll
    for (int r = 0; r < NREL; r++) acc[r] = 0.f;

    const int ibase = by * ICHUNK;
#pragma unroll 4
    for (int ii = 0; ii < ICHUNK; ii++) {
        float w1 = W1[(ibase + ii) * DIM2 + j];   // coalesced over tx
#pragma unroll
        for (int r = 0; r < NREL; r++) acc[r] += sW2[r][ii] * w1;
    }
#pragma unroll
    for (int r = 0; r < NREL; r++)
        g_Mpart[(by * NREL + r) * DIM2 + j] = acc[r];
}

// ---------------------------------------------------------------------------
// Stage B: deterministic fixed-order reduction over the 16 i-chunks.
// Block 0 additionally computes c[r] = W2[r]·b1 + b2[r] (independent work).
// ---------------------------------------------------------------------------
__global__ void m_reduce_kernel(const float* __restrict__ W2,
                                const float* __restrict__ b1,
                                const float* __restrict__ b2) {
    const int g = blockIdx.x * 256 + threadIdx.x;  // 0..16383
    float s = 0.f;
#pragma unroll
    for (int by = 0; by < NI_CHUNK; by++)
        s += g_Mpart[by * (NREL * DIM2) + g];
    g_M[g] = s;

    if (blockIdx.x == 0) {
        const int w    = threadIdx.x >> 5;   // 0..7 -> r
        const int lane = threadIdx.x & 31;
        float t = 0.f;
        for (int i = lane; i < DIM; i += 32) t += b1[i] * W2[w * DIM + i];
#pragma unroll
        for (int off = 16; off; off >>= 1)
            t += __shfl_xor_sync(0xffffffffu, t, off);
        if (lane == 0) g_c[w] = t + b2[w];
    }
}

// ---------------------------------------------------------------------------
// U table: U[o][j] = feats[o] · Mrow_j
//   j in [0,8):  Mrow_j = M[j][0:1024]      (subject projection)
//   j in [8,16): Mrow_j = M[j-8][1024:2048] (object projection)
// Warp layout: warp w -> pair = w>>1 (4 objects), half = w&1 (8 j-columns).
// Packed f32x2 FMAs, 64-reg accumulator file, butterfly-fold reduction.
// grid 256 x 256 threads -> 2048 warps.
// ---------------------------------------------------------------------------
__global__ void __launch_bounds__(256) u_kernel(const float* __restrict__ feats) {
    const int gw   = (blockIdx.x * 256 + threadIdx.x) >> 5;  // 0..2047
    const int lane = threadIdx.x & 31;
    const int pair = gw >> 1;          // 0..1023
    const int half = gw & 1;           // 0: sub cols, 1: obj cols
    const int obase = pair * 4;

    const longlong2* __restrict__ F2 = (const longlong2*)feats;  // 256 per row
    const longlong2* __restrict__ M2 = (const longlong2*)g_M;    // row j at j*512
    const int jbase = half * 256;      // +1024 floats for obj half

    unsigned long long acc[4][8];
#pragma unroll
    for (int k = 0; k < 4; k++)
#pragma unroll
        for (int j = 0; j < 8; j++) acc[k][j] = 0ull;  // (0.0f, 0.0f)

#pragma unroll 1
    for (int t = 0; t < 8; t++) {      // 8 x 32 lanes x 4 floats = 1024 d
        const int idx = t * 32 + lane;
        unsigned long long fa[4], fb[4];
#pragma unroll
        for (int k = 0; k < 4; k++) {
            longlong2 fv = __ldg(F2 + (obase + k) * 256 + idx);
            fa[k] = (unsigned long long)fv.x;
            fb[k] = (unsigned long long)fv.y;
        }
#pragma unroll
        for (int j = 0; j < 8; j++) {
            longlong2 mv = __ldg(M2 + j * 512 + jbase + idx);
            const unsigned long long ma = (unsigned long long)mv.x;
            const unsigned long long mb = (unsigned long long)mv.y;
#pragma unroll
            for (int k = 0; k < 4; k++) {
                ffma2(acc[k][j], fa[k], ma);
                ffma2(acc[k][j], fb[k], mb);
            }
        }
    }

    // Collapse packed halves -> 32 scalar partials per lane, index vi = k*8+j.
    float v[32];
#pragma unroll
    for (int k = 0; k < 4; k++)
#pragma unroll
        for (int j = 0; j < 8; j++) {
            float2 p = *(float2*)&acc[k][j];
            v[k * 8 + j] = p.x + p.y;
        }

    // Butterfly fold: 5 stages, 31 shfl. After stage s with xor-distance d,
    // lane bit d selects the surviving half. Lane L ends with the full
    // 32-lane sum of original index bitrev5(L) in v[0].
    int nv = 32;
#pragma unroll
    for (int d = 1; d < 32; d <<= 1) {
        nv >>= 1;
        const bool up = (lane & d) != 0;
#pragma unroll
        for (int i = 0; i < 16; i++) {
            if (i < nv) {
                float send = up ? v[i] : v[i + nv];
                float recv = __shfl_xor_sync(0xffffffffu, send, d);
                v[i] = (up ? v[i + nv] : v[i]) + recv;
            }
        }
    }

    const int vi = __brev(lane) >> 27;   // bitrev5
    const int k = vi >> 3;
    const int j = vi & 7;
    g_U[(obase + k) * 16 + half * 8 + j] = v[0];
}

// ---------------------------------------------------------------------------
// out[p][r] = U[s_p][r] + U[o_p][8+r] + c[r]   (pairs are int32)
// ---------------------------------------------------------------------------
__global__ void gather_kernel(const int* __restrict__ pairs,
                              float* __restrict__ out) {
    const int p = blockIdx.x * 256 + threadIdx.x;  // 0..65535
    int2 pr = ((const int2*)pairs)[p];
    const int s = pr.x;
    const int o = pr.y;
    const float4* __restrict__ U4 = (const float4*)g_U;
    float4 a0 = U4[s * 4 + 0];
    float4 a1 = U4[s * 4 + 1];
    float4 b0 = U4[o * 4 + 2];
    float4 b1 = U4[o * 4 + 3];
    float4 c0 = ((const float4*)g_c)[0];
    float4 c1 = ((const float4*)g_c)[1];
    float4 o0, o1;
    o0.x = a0.x + b0.x + c0.x;  o0.y = a0.y + b0.y + c0.y;
    o0.z = a0.z + b0.z + c0.z;  o0.w = a0.w + b0.w + c0.w;
    o1.x = a1.x + b1.x + c1.x;  o1.y = a1.y + b1.y + c1.y;
    o1.z = a1.z + b1.z + c1.z;  o1.w = a1.w + b1.w + c1.w;
    ((float4*)out)[p * 2 + 0] = o0;
    ((float4*)out)[p * 2 + 1] = o1;
}

extern "C" void kernel_launch(void* const* d_in, const int* in_sizes, int n_in,
                              void* d_out, int out_size) {
    const float* feats = (const float*)d_in[0];   // (4096, 1024) f32
    const int*   pairs = (const int*)d_in[1];     // (65536, 2) i32
    const float* W1    = (const float*)d_in[2];   // (1024, 2048) f32
    const float* b1    = (const float*)d_in[3];   // (1024,) f32
    const float* W2    = (const float*)d_in[4];   // (8, 1024) f32
    const float* b2    = (const float*)d_in[5];   // (8,) f32
    float*       out   = (float*)d_out;           // (65536, 8) f32

    m_partial_kernel<<<dim3(8, 16), 256>>>(W1, W2);
    m_reduce_kernel<<<64, 256>>>(W2, b1, b2);
    u_kernel<<<256, 256>>>(feats);
    gather_kernel<<<256, 256>>>(pairs, out);
}

// round 4
// speedup vs baseline: 1.3134x; 1.0353x over previous
#include <cuda_runtime.h>

#define NOBJ   4096
#define DIM    1024
#define DIM2   2048
#define NREL   8
#define NPAIR  65536

// Scratch (device globals — no allocation allowed)
__device__ float g_M[NREL * DIM2];   // fused weight M = W2 @ W1, 64 KB
__device__ float g_c[NREL];          // fused bias c = W2@b1 + b2
__device__ float g_U[NOBJ * 16];     // per-object projections, 256 KB
                                     //   [o][0:8]  = feats[o]·M[:, :1024]ᵀ
                                     //   [o][8:16] = feats[o]·M[:, 1024:]ᵀ + c

// Packed fp32x2 FMA: d = a*b + d elementwise on (lo,hi) pairs.
__device__ __forceinline__ void ffma2(unsigned long long& acc,
                                      unsigned long long a,
                                      unsigned long long b) {
    asm("fma.rn.f32x2 %0, %1, %2, %0;" : "+l"(acc) : "l"(a), "l"(b));
}

// ---------------------------------------------------------------------------
// M[r][j] = sum_i W2[r][i] * W1[i][j]  (+ block 0 computes c = W2·b1 + b2)
// Grid 128 x 256. Block b owns 16 j-columns; thread (jloc = t&15, ic = t>>4)
// accumulates 64 i's, then an in-block fixed-order smem reduction over the
// 16 i-chunks. W1 (8 MB) is read exactly once, coalesced.
// ---------------------------------------------------------------------------
__global__ void __launch_bounds__(256) m_kernel(const float* __restrict__ W1,
                                                const float* __restrict__ W2,
                                                const float* __restrict__ b1,
                                                const float* __restrict__ b2) {
    __shared__ float sW2[NREL][DIM];       // 32 KB
    __shared__ float sAcc[16][NREL][16];   // 8 KB  [ichunk][r][jloc]
    const int tx = threadIdx.x;

    const float4* __restrict__ W24 = (const float4*)W2;
    float4* sW24 = (float4*)&sW2[0][0];
    for (int i = tx; i < (NREL * DIM) / 4; i += 256) sW24[i] = W24[i];
    __syncthreads();

    const int jloc  = tx & 15;
    const int ic    = tx >> 4;                 // 0..15
    const int j     = blockIdx.x * 16 + jloc;
    const int ibase = ic * 64;

    float acc[NREL];
#pragma unroll
    for (int r = 0; r < NREL; r++) acc[r] = 0.f;

#pragma unroll 8
    for (int ii = 0; ii < 64; ii++) {
        const int i = ibase + ii;
        float w1 = __ldg(&W1[i * DIM2 + j]);
#pragma unroll
        for (int r = 0; r < NREL; r++) acc[r] += sW2[r][i] * w1;
    }
#pragma unroll
    for (int r = 0; r < NREL; r++) sAcc[ic][r][jloc] = acc[r];
    __syncthreads();

    if (tx < 128) {
        const int r = tx >> 4, jl = tx & 15;
        float s = 0.f;
#pragma unroll
        for (int c = 0; c < 16; c++) s += sAcc[c][r][jl];   // fixed order
        g_M[r * DIM2 + blockIdx.x * 16 + jl] = s;
    }

    if (blockIdx.x == 0) {                 // c[r] = W2[r]·b1 + b2[r]
        const int w = tx >> 5, lane = tx & 31;
        float t = 0.f;
        for (int i = lane; i < DIM; i += 32) t += b1[i] * sW2[w][i];
#pragma unroll
        for (int off = 16; off; off >>= 1)
            t += __shfl_xor_sync(0xffffffffu, t, off);
        if (lane == 0) g_c[w] = t + b2[w];
    }
}

// ---------------------------------------------------------------------------
// U table: U[o][j] = feats[o] · Mrow_j   (+ c[j] folded into the object half)
// Warp w -> pair = w>>1 (4 objects), half = w&1 (8 j-columns).
// Packed f32x2 FMAs, butterfly-fold reduction. Grid 256 x 256 (2048 warps).
// ---------------------------------------------------------------------------
__global__ void __launch_bounds__(256) u_kernel(const float* __restrict__ feats) {
    const int gw   = (blockIdx.x * 256 + threadIdx.x) >> 5;  // 0..2047
    const int lane = threadIdx.x & 31;
    const int pair = gw >> 1;
    const int half = gw & 1;           // 0: sub cols, 1: obj cols
    const int obase = pair * 4;

    const longlong2* __restrict__ F2 = (const longlong2*)feats;  // 256 per row
    const longlong2* __restrict__ M2 = (const longlong2*)g_M;    // row j at j*512
    const int jbase = half * 256;      // +1024 floats for obj half

    unsigned long long acc[4][8];
#pragma unroll
    for (int k = 0; k < 4; k++)
#pragma unroll
        for (int j = 0; j < 8; j++) acc[k][j] = 0ull;

#pragma unroll 1
    for (int t = 0; t < 8; t++) {      // 8 x 32 lanes x 4 floats = 1024 d
        const int idx = t * 32 + lane;
        unsigned long long fa[4], fb[4];
#pragma unroll
        for (int k = 0; k < 4; k++) {
            longlong2 fv = __ldg(F2 + (obase + k) * 256 + idx);
            fa[k] = (unsigned long long)fv.x;
            fb[k] = (unsigned long long)fv.y;
        }
#pragma unroll
        for (int j = 0; j < 8; j++) {
            longlong2 mv = __ldg(M2 + j * 512 + jbase + idx);
            const unsigned long long ma = (unsigned long long)mv.x;
            const unsigned long long mb = (unsigned long long)mv.y;
#pragma unroll
            for (int k = 0; k < 4; k++) {
                ffma2(acc[k][j], fa[k], ma);
                ffma2(acc[k][j], fb[k], mb);
            }
        }
    }

    // Collapse packed halves -> 32 scalar partials per lane (vi = k*8+j).
    float v[32];
#pragma unroll
    for (int k = 0; k < 4; k++)
#pragma unroll
        for (int j = 0; j < 8; j++) {
            float2 p = *(float2*)&acc[k][j];
            v[k * 8 + j] = p.x + p.y;
        }

    // Butterfly fold: 5 stages, 31 shfl. Lane L ends with the full sum of
    // original index bitrev5(L) in v[0].
    int nv = 32;
#pragma unroll
    for (int d = 1; d < 32; d <<= 1) {
        nv >>= 1;
        const bool up = (lane & d) != 0;
#pragma unroll
        for (int i = 0; i < 16; i++) {
            if (i < nv) {
                float send = up ? v[i] : v[i + nv];
                float recv = __shfl_xor_sync(0xffffffffu, send, d);
                v[i] = (up ? v[i + nv] : v[i]) + recv;
            }
        }
    }

    const int vi = __brev(lane) >> 27;   // bitrev5
    const int k = vi >> 3;
    const int j = vi & 7;
    const float bias = half ? g_c[j] : 0.f;   // fold c into object half
    g_U[(obase + k) * 16 + half * 8 + j] = v[0] + bias;
}

// ---------------------------------------------------------------------------
// out[p][r] = U[s_p][r] + U[o_p][8+r]   (c already folded into U's obj half)
// 4 pairs per thread: batched pair loads, then 16 independent U loads (MLP).
// Grid 64 x 256.
// ---------------------------------------------------------------------------
__global__ void __launch_bounds__(256) gather_kernel(const int* __restrict__ pairs,
                                                     float* __restrict__ out) {
    const int base = (blockIdx.x * 256 + threadIdx.x) * 4;   // first pair idx
    const int4* __restrict__ P4 = (const int4*)pairs;        // 2 pairs / int4
    int4 pa = __ldg(&P4[(base >> 1) + 0]);
    int4 pb = __ldg(&P4[(base >> 1) + 1]);
    const int s[4] = {pa.x, pa.z, pb.x, pb.z};
    const int o[4] = {pa.y, pa.w, pb.y, pb.w};

    const float4* __restrict__ U4 = (const float4*)g_U;
    float4 a0[4], a1[4], b0[4], b1[4];
#pragma unroll
    for (int k = 0; k < 4; k++) {       // all 16 loads independent
        a0[k] = __ldg(&U4[s[k] * 4 + 0]);
        a1[k] = __ldg(&U4[s[k] * 4 + 1]);
        b0[k] = __ldg(&U4[o[k] * 4 + 2]);
        b1[k] = __ldg(&U4[o[k] * 4 + 3]);
    }
    float4* __restrict__ O4 = (float4*)out;
#pragma unroll
    for (int k = 0; k < 4; k++) {
        float4 r0, r1;
        r0.x = a0[k].x + b0[k].x;  r0.y = a0[k].y + b0[k].y;
        r0.z = a0[k].z + b0[k].z;  r0.w = a0[k].w + b0[k].w;
        r1.x = a1[k].x + b1[k].x;  r1.y = a1[k].y + b1[k].y;
        r1.z = a1[k].z + b1[k].z;  r1.w = a1[k].w + b1[k].w;
        O4[(base + k) * 2 + 0] = r0;
        O4[(base + k) * 2 + 1] = r1;
    }
}

extern "C" void kernel_launch(void* const* d_in, const int* in_sizes, int n_in,
                              void* d_out, int out_size) {
    const float* feats = (const float*)d_in[0];   // (4096, 1024) f32
    const int*   pairs = (const int*)d_in[1];     // (65536, 2) i32
    const float* W1    = (const float*)d_in[2];   // (1024, 2048) f32
    const float* b1    = (const float*)d_in[3];   // (1024,) f32
    const float* W2    = (const float*)d_in[4];   // (8, 1024) f32
    const float* b2    = (const float*)d_in[5];   // (8,) f32
    float*       out   = (float*)d_out;           // (65536, 8) f32

    m_kernel<<<128, 256>>>(W1, W2, b1, b2);
    u_kernel<<<256, 256>>>(feats);
    gather_kernel<<<64, 256>>>(pairs, out);
}